// round 4
// baseline (speedup 1.0000x reference)
#include <cuda_runtime.h>

#define B_      256
#define SEQ_    128
#define HID_    1024
#define NB_     256
#define NL_     3
#define KW_     8              // k-values per CTA (one per warp)
#define CHUNKS_ 16             // b-chunks (split softmax)
#define BPC_    (B_/CHUNKS_)   // 16 b per chunk

// Scratch (static device arrays only — no cudaMalloc allowed)
__device__ float g_part_u[NB_][CHUNKS_][HID_];   // 16 MB
__device__ float g_part_m[NB_][CHUNKS_];
__device__ float g_part_z[NB_][CHUNKS_];
__device__ float g_u[NB_][HID_];                 // 1 MB
__device__ float g_RH[NL_][HID_];                // R_w @ H_w  (3 x 1024)
__device__ float g_act[B_][HID_];                // slow-path activations
__device__ int   g_flag;                         // 1 iff alpha == 1 everywhere

// ---------------------------------------------------------------------------
// K1: one WARP per (k, chunk); fully barrier-free, high occupancy (3 CTA/SM).
// Per b: pass A streams x row + S row from GMEM (dot + shfl reduce),
//        pass B re-reads the S row (L1 hit) and FMAs into acc[8] (32 regs).
// Online softmax in branchless FMA form (coefficients are warp-uniform).
// Grid (NB_/KW_, CHUNKS_) = (32,16), 256 threads.
// ---------------------------------------------------------------------------
__global__ __launch_bounds__(256, 3) void k1_partials(
    const float* __restrict__ ee, const float* __restrict__ S)
{
    const int w    = threadIdx.x >> 5;
    const int lane = threadIdx.x & 31;
    const int k    = blockIdx.x * KW_ + w;
    const int c    = blockIdx.y;
    const int b0   = c * BPC_;
    const int hoff = lane * 4;

    float4 acc[8];
#pragma unroll
    for (int j = 0; j < 8; j++) acc[j] = make_float4(0.f, 0.f, 0.f, 0.f);
    float m = -3.0e38f, z = 0.f;

    for (int bi = 0; bi < BPC_; bi++) {
        const int b = b0 + bi;
        const float* __restrict__ xr = ee + (size_t)b * SEQ_ * HID_;
        const float* __restrict__ sr = S + ((size_t)b * NB_ + k) * HID_;

        // pass A: dot x[b] . S[b,k]  (streams both rows; S lands in L1)
        float d = 0.f;
#pragma unroll
        for (int j = 0; j < 8; j++) {
            const float4 xv = *(const float4*)(xr + j * 128 + hoff);
            const float4 sv = *(const float4*)(sr + j * 128 + hoff);
            d += xv.x * sv.x + xv.y * sv.y + xv.z * sv.z + xv.w * sv.w;
        }
#pragma unroll
        for (int off = 16; off > 0; off >>= 1)
            d += __shfl_xor_sync(0xffffffffu, d, off);

        // branchless online softmax coefficients (warp-uniform)
        const float mn = fmaxf(m, d);
        const float cf = __expf(m - mn);   // scale on old acc (1 or exp<1; 0 on first iter)
        const float wg = __expf(d - mn);   // weight on new row
        z = z * cf + wg;
        m = mn;

        // pass B: re-read S row (L1 hit) and accumulate
#pragma unroll
        for (int j = 0; j < 8; j++) {
            const float4 sv = *(const float4*)(sr + j * 128 + hoff);
            acc[j].x = acc[j].x * cf + wg * sv.x;
            acc[j].y = acc[j].y * cf + wg * sv.y;
            acc[j].z = acc[j].z * cf + wg * sv.z;
            acc[j].w = acc[j].w * cf + wg * sv.w;
        }
    }

#pragma unroll
    for (int j = 0; j < 8; j++)
        *(float4*)&g_part_u[k][c][j * 128 + hoff] = acc[j];
    if (lane == 0) { g_part_m[k][c] = m; g_part_z[k][c] = z; }
}

// ---------------------------------------------------------------------------
// KMIX: blocks 0..255 combine split-softmax partials into u[k][:]
//       (block 0 also computes the alpha==1 flag);
//       blocks 256..258 compute RH[l][:] = R_w[l] @ H_w.
// ---------------------------------------------------------------------------
__global__ __launch_bounds__(256) void kmix(
    const float* __restrict__ alpha, const float* __restrict__ Rw,
    const float* __restrict__ Hw)
{
    const int bid = blockIdx.x;
    const int t = threadIdx.x;

    if (bid < NB_) {
        const int k = bid;
        const int h4 = t * 4;

        if (k == 0) {
            int ok = 1;
#pragma unroll
            for (int r = 0; r < 4; r++) ok &= (alpha[h4 + r] == 1.0f);
            ok = __syncthreads_and(ok);
            if (t == 0) g_flag = ok;
        }

        float m = -3.0e38f;
#pragma unroll
        for (int c = 0; c < CHUNKS_; c++) m = fmaxf(m, g_part_m[k][c]);
        float Z = 0.f, w[CHUNKS_];
#pragma unroll
        for (int c = 0; c < CHUNKS_; c++) {
            w[c] = __expf(g_part_m[k][c] - m);
            Z += g_part_z[k][c] * w[c];
        }
        const float inv = 1.f / Z;
        float4 s = make_float4(0.f, 0.f, 0.f, 0.f);
#pragma unroll
        for (int c = 0; c < CHUNKS_; c++) {
            const float4 p = *(const float4*)&g_part_u[k][c][h4];
            const float ww = w[c] * inv;
            s.x += ww * p.x; s.y += ww * p.y; s.z += ww * p.z; s.w += ww * p.w;
        }
        *(float4*)&g_u[k][h4] = s;
    } else {
        const int l = bid - NB_;
        const int j4 = t * 4;
        float4 s = make_float4(0.f, 0.f, 0.f, 0.f);
#pragma unroll 8
        for (int h = 0; h < HID_; h++) {
            const float r = __ldg(Rw + l * HID_ + h);
            const float4 hv = *(const float4*)(Hw + (size_t)h * HID_ + j4);
            s.x += r * hv.x; s.y += r * hv.y; s.z += r * hv.z; s.w += r * hv.w;
        }
        *(float4*)&g_RH[l][j4] = s;
    }
}

// ---------------------------------------------------------------------------
// Fast path (alpha == 1): out[i][l] = x[i]·R_w[l] + u[i]·RH[l]
// ---------------------------------------------------------------------------
__global__ __launch_bounds__(256) void k_fast(
    const float* __restrict__ ee, const float* __restrict__ Rw,
    float* __restrict__ out)
{
    if (!g_flag) return;
    const int w = (blockIdx.x * 256 + threadIdx.x) >> 5;
    if (w >= B_ * NL_) return;
    const int i = w / NL_;
    const int l = w % NL_;
    const int lane = threadIdx.x & 31;
    const float* xr = ee + (size_t)i * SEQ_ * HID_;
    float s = 0.f;
#pragma unroll
    for (int j0 = 0; j0 < HID_; j0 += 128) {
        const int j = j0 + lane * 4;
        const float4 xv = *(const float4*)(xr + j);
        const float4 rv = *(const float4*)(Rw + l * HID_ + j);
        const float4 uv = *(const float4*)&g_u[i][j];
        const float4 gv = *(const float4*)&g_RH[l][j];
        s += xv.x * rv.x + xv.y * rv.y + xv.z * rv.z + xv.w * rv.w
           + uv.x * gv.x + uv.y * gv.y + uv.z * gv.z + uv.w * gv.w;
    }
#pragma unroll
    for (int off = 16; off > 0; off >>= 1)
        s += __shfl_xor_sync(0xffffffffu, s, off);
    if (lane == 0) out[i * NL_ + l] = s;
}

// ---------------------------------------------------------------------------
// Slow path (general alpha): v = x + u@H^T, act = PReLU(v) -> g_act.
// ---------------------------------------------------------------------------
__global__ __launch_bounds__(256) void k3_full(
    const float* __restrict__ ee, const float* __restrict__ Hw,
    const float* __restrict__ alpha)
{
    if (g_flag) return;
    __shared__ float Us[32][33];
    __shared__ float Hs[32][33];
    const int t  = threadIdx.x;
    const int tx = t & 15, ty = t >> 4;
    const int i0 = blockIdx.x * 32, h0 = blockIdx.y * 32;
    const int lr = t >> 3;
    const int lc = (t & 7) * 4;
    float acc00 = 0.f, acc01 = 0.f, acc10 = 0.f, acc11 = 0.f;

    for (int kk = 0; kk < HID_; kk += 32) {
        const float4 uu = *(const float4*)&g_u[i0 + lr][kk + lc];
        const float4 hh = *(const float4*)(Hw + (size_t)(h0 + lr) * HID_ + kk + lc);
        Us[lr][lc] = uu.x; Us[lr][lc+1] = uu.y; Us[lr][lc+2] = uu.z; Us[lr][lc+3] = uu.w;
        Hs[lr][lc] = hh.x; Hs[lr][lc+1] = hh.y; Hs[lr][lc+2] = hh.z; Hs[lr][lc+3] = hh.w;
        __syncthreads();
#pragma unroll
        for (int j = 0; j < 32; j++) {
            const float a0 = Us[ty*2][j],   a1 = Us[ty*2+1][j];
            const float b0 = Hs[tx*2][j],   b1 = Hs[tx*2+1][j];
            acc00 += a0*b0; acc01 += a0*b1; acc10 += a1*b0; acc11 += a1*b1;
        }
        __syncthreads();
    }
    const float accs[2][2] = { {acc00, acc01}, {acc10, acc11} };
#pragma unroll
    for (int ii = 0; ii < 2; ii++)
#pragma unroll
        for (int jj = 0; jj < 2; jj++) {
            const int i = i0 + ty*2 + ii;
            const int h = h0 + tx*2 + jj;
            const float v = accs[ii][jj] + ee[(size_t)i * SEQ_ * HID_ + h];
            g_act[i][h] = (v >= 0.f) ? v : alpha[h] * v;
        }
}

__global__ __launch_bounds__(256) void k4_full(
    const float* __restrict__ Rw, float* __restrict__ out)
{
    if (g_flag) return;
    const int w = (blockIdx.x * 256 + threadIdx.x) >> 5;
    if (w >= B_ * NL_) return;
    const int i = w / NL_;
    const int l = w % NL_;
    const int lane = threadIdx.x & 31;
    float s = 0.f;
#pragma unroll 8
    for (int j = lane; j < HID_; j += 32)
        s += g_act[i][j] * Rw[l * HID_ + j];
#pragma unroll
    for (int off = 16; off > 0; off >>= 1)
        s += __shfl_xor_sync(0xffffffffu, s, off);
    if (lane == 0) out[i * NL_ + l] = s;
}

// ---------------------------------------------------------------------------
extern "C" void kernel_launch(void* const* d_in, const int* in_sizes, int n_in,
                              void* d_out, int out_size)
{
    const float* ee = (const float*)d_in[0];   // (256,128,1024)
    const float* S  = (const float*)d_in[1];   // (256, 256*1024)
    const float* Hw = (const float*)d_in[2];   // (1024,1024)
    const float* Rw = (const float*)d_in[3];   // (3,1024)
    const float* al = (const float*)d_in[4];   // (1024,)
    float* out = (float*)d_out;                // (256,3)

    k1_partials<<<dim3(NB_ / KW_, CHUNKS_), 256>>>(ee, S);
    kmix<<<NB_ + NL_, 256>>>(al, Rw, Hw);
    k3_full<<<dim3(B_ / 32, HID_ / 32), 256>>>(ee, Hw, al);
    k4_full<<<(B_ * NL_ * 32) / 256, 256>>>(Rw, out);
    k_fast<<<(B_ * NL_ * 32) / 256, 256>>>(ee, Rw, out);
}

// round 5
// speedup vs baseline: 1.1180x; 1.1180x over previous
#include <cuda_runtime.h>

#define B_      256
#define SEQ_    128
#define HID_    1024
#define NB_     256
#define NL_     3
#define G_      4              // k-values per CTA
#define CHUNKS_ 32             // b-chunks (split softmax)
#define BPC_    (B_/CHUNKS_)   // 8 b per chunk

// Scratch (static device arrays only — no cudaMalloc allowed)
__device__ float g_part_u[NB_][CHUNKS_][HID_];   // 32 MB
__device__ float g_part_m[NB_][CHUNKS_];
__device__ float g_part_z[NB_][CHUNKS_];
__device__ float g_u[NB_][HID_];                 // 1 MB
__device__ float g_RH[NL_][HID_];                // R_w @ H_w  (3 x 1024)
__device__ float g_act[B_][HID_];                // slow-path activations
__device__ int   g_flag;                         // 1 iff alpha == 1 everywhere

// ---------------------------------------------------------------------------
// K1 two-phase, chunk-local softmax. CTA = (4 k's, 8 b's). 256 threads,
// thread t owns h4 = 4t. Phase 1 streams x+S once (DRAM), keeping only 32
// score-partial registers. One batched block reduction per chunk. Phase 2
// re-reads the same 32 S rows — L2-resident (128 KB/CTA) — and accumulates
// acc[4] (16 regs). No per-iteration barriers, no register spill.
// Grid (NB_/G_, CHUNKS_) = (64, 32) = 2048 CTAs.
// ---------------------------------------------------------------------------
__global__ __launch_bounds__(256) void k1_partials(
    const float* __restrict__ ee, const float* __restrict__ S)
{
    const int t     = threadIdx.x;
    const int w     = t >> 5;
    const int lane  = t & 31;
    const int kbase = blockIdx.x * G_;
    const int c     = blockIdx.y;
    const int b0    = c * BPC_;
    const int h4    = t * 4;

    __shared__ float sred[8 * BPC_ * G_];   // [warp][b][g] warp partials
    __shared__ float swgt[BPC_][G_];        // softmax weights exp(s - m)

    // ---- phase 1: score partials (only persistent state: d[8][4]) ----
    float d[BPC_][G_];
#pragma unroll
    for (int b = 0; b < BPC_; b++)
#pragma unroll
        for (int g = 0; g < G_; g++) d[b][g] = 0.f;

#pragma unroll
    for (int b = 0; b < BPC_; b++) {
        const int bb = b0 + b;
        const float4 xv = *(const float4*)(ee + (size_t)bb * SEQ_ * HID_ + h4);
        const float* __restrict__ sb = S + ((size_t)bb * NB_ + kbase) * HID_ + h4;
#pragma unroll
        for (int g = 0; g < G_; g++) {
            const float4 sv = *(const float4*)(sb + (size_t)g * HID_);
            d[b][g] += xv.x * sv.x + xv.y * sv.y + xv.z * sv.z + xv.w * sv.w;
        }
    }

    // ---- batched reduce: warp-level shfl, then 4 warps finish softmax ----
#pragma unroll
    for (int b = 0; b < BPC_; b++)
#pragma unroll
        for (int g = 0; g < G_; g++) {
            float v = d[b][g];
#pragma unroll
            for (int off = 16; off > 0; off >>= 1)
                v += __shfl_xor_sync(0xffffffffu, v, off);
            if (lane == 0) sred[w * (BPC_ * G_) + b * G_ + g] = v;
        }
    __syncthreads();

    if (w < G_) {                       // warp w owns k = kbase + w
        float s = -3.0e38f;
        if (lane < BPC_) {
            float v = 0.f;
#pragma unroll
            for (int ww = 0; ww < 8; ww++)
                v += sred[ww * (BPC_ * G_) + lane * G_ + w];
            s = v;
        }
        // reduce over the 8-lane octet (lanes 0..7)
        float m = s;
#pragma unroll
        for (int off = 4; off > 0; off >>= 1)
            m = fmaxf(m, __shfl_xor_sync(0xffffffffu, m, off));
        const float e = (lane < BPC_) ? __expf(s - m) : 0.f;
        float z = e;
#pragma unroll
        for (int off = 4; off > 0; off >>= 1)
            z += __shfl_xor_sync(0xffffffffu, z, off);
        if (lane < BPC_) swgt[lane][w] = e;
        if (lane == 0) {
            g_part_m[kbase + w][c] = m;
            g_part_z[kbase + w][c] = z;
        }
    }
    __syncthreads();

    // ---- phase 2: weighted accumulation; S rows hit L2 ----
    float4 acc[G_];
#pragma unroll
    for (int g = 0; g < G_; g++) acc[g] = make_float4(0.f, 0.f, 0.f, 0.f);

#pragma unroll
    for (int b = 0; b < BPC_; b++) {
        const int bb = b0 + b;
        const float* __restrict__ sb = S + ((size_t)bb * NB_ + kbase) * HID_ + h4;
#pragma unroll
        for (int g = 0; g < G_; g++) {
            const float4 sv = *(const float4*)(sb + (size_t)g * HID_);
            const float wgt = swgt[b][g];
            acc[g].x += wgt * sv.x;
            acc[g].y += wgt * sv.y;
            acc[g].z += wgt * sv.z;
            acc[g].w += wgt * sv.w;
        }
    }
#pragma unroll
    for (int g = 0; g < G_; g++)
        *(float4*)&g_part_u[kbase + g][c][h4] = acc[g];
}

// ---------------------------------------------------------------------------
// KMIX: blocks 0..255 combine split-softmax partials into u[k][:]
//       (block 0 also computes the alpha==1 flag);
//       blocks 256..258 compute RH[l][:] = R_w[l] @ H_w.
// ---------------------------------------------------------------------------
__global__ __launch_bounds__(256) void kmix(
    const float* __restrict__ alpha, const float* __restrict__ Rw,
    const float* __restrict__ Hw)
{
    const int bid = blockIdx.x;
    const int t = threadIdx.x;

    if (bid < NB_) {
        const int k = bid;
        const int h4 = t * 4;

        if (k == 0) {
            int ok = 1;
#pragma unroll
            for (int r = 0; r < 4; r++) ok &= (alpha[h4 + r] == 1.0f);
            ok = __syncthreads_and(ok);
            if (t == 0) g_flag = ok;
        }

        float m = -3.0e38f;
#pragma unroll
        for (int c = 0; c < CHUNKS_; c++) m = fmaxf(m, g_part_m[k][c]);
        float Z = 0.f;
        float w[CHUNKS_];
#pragma unroll
        for (int c = 0; c < CHUNKS_; c++) {
            w[c] = __expf(g_part_m[k][c] - m);
            Z += g_part_z[k][c] * w[c];
        }
        const float inv = 1.f / Z;
        float4 s = make_float4(0.f, 0.f, 0.f, 0.f);
#pragma unroll
        for (int c = 0; c < CHUNKS_; c++) {
            const float4 p = *(const float4*)&g_part_u[k][c][h4];
            const float ww = w[c] * inv;
            s.x += ww * p.x; s.y += ww * p.y; s.z += ww * p.z; s.w += ww * p.w;
        }
        *(float4*)&g_u[k][h4] = s;
    } else {
        const int l = bid - NB_;
        const int j4 = t * 4;
        float4 s = make_float4(0.f, 0.f, 0.f, 0.f);
#pragma unroll 8
        for (int h = 0; h < HID_; h++) {
            const float r = __ldg(Rw + l * HID_ + h);
            const float4 hv = *(const float4*)(Hw + (size_t)h * HID_ + j4);
            s.x += r * hv.x; s.y += r * hv.y; s.z += r * hv.z; s.w += r * hv.w;
        }
        *(float4*)&g_RH[l][j4] = s;
    }
}

// ---------------------------------------------------------------------------
// Fast path (alpha == 1): out[i][l] = x[i]·R_w[l] + u[i]·RH[l]
// ---------------------------------------------------------------------------
__global__ __launch_bounds__(256) void k_fast(
    const float* __restrict__ ee, const float* __restrict__ Rw,
    float* __restrict__ out)
{
    if (!g_flag) return;
    const int w = (blockIdx.x * 256 + threadIdx.x) >> 5;
    if (w >= B_ * NL_) return;
    const int i = w / NL_;
    const int l = w % NL_;
    const int lane = threadIdx.x & 31;
    const float* xr = ee + (size_t)i * SEQ_ * HID_;
    float s = 0.f;
#pragma unroll
    for (int j0 = 0; j0 < HID_; j0 += 128) {
        const int j = j0 + lane * 4;
        const float4 xv = *(const float4*)(xr + j);
        const float4 rv = *(const float4*)(Rw + l * HID_ + j);
        const float4 uv = *(const float4*)&g_u[i][j];
        const float4 gv = *(const float4*)&g_RH[l][j];
        s += xv.x * rv.x + xv.y * rv.y + xv.z * rv.z + xv.w * rv.w
           + uv.x * gv.x + uv.y * gv.y + uv.z * gv.z + uv.w * gv.w;
    }
#pragma unroll
    for (int off = 16; off > 0; off >>= 1)
        s += __shfl_xor_sync(0xffffffffu, s, off);
    if (lane == 0) out[i * NL_ + l] = s;
}

// ---------------------------------------------------------------------------
// Slow path (general alpha): v = x + u@H^T, act = PReLU(v) -> g_act.
// ---------------------------------------------------------------------------
__global__ __launch_bounds__(256) void k3_full(
    const float* __restrict__ ee, const float* __restrict__ Hw,
    const float* __restrict__ alpha)
{
    if (g_flag) return;
    __shared__ float Us[32][33];
    __shared__ float Hs[32][33];
    const int t  = threadIdx.x;
    const int tx = t & 15, ty = t >> 4;
    const int i0 = blockIdx.x * 32, h0 = blockIdx.y * 32;
    const int lr = t >> 3;
    const int lc = (t & 7) * 4;
    float acc00 = 0.f, acc01 = 0.f, acc10 = 0.f, acc11 = 0.f;

    for (int kk = 0; kk < HID_; kk += 32) {
        const float4 uu = *(const float4*)&g_u[i0 + lr][kk + lc];
        const float4 hh = *(const float4*)(Hw + (size_t)(h0 + lr) * HID_ + kk + lc);
        Us[lr][lc] = uu.x; Us[lr][lc+1] = uu.y; Us[lr][lc+2] = uu.z; Us[lr][lc+3] = uu.w;
        Hs[lr][lc] = hh.x; Hs[lr][lc+1] = hh.y; Hs[lr][lc+2] = hh.z; Hs[lr][lc+3] = hh.w;
        __syncthreads();
#pragma unroll
        for (int j = 0; j < 32; j++) {
            const float a0 = Us[ty*2][j],   a1 = Us[ty*2+1][j];
            const float b0 = Hs[tx*2][j],   b1 = Hs[tx*2+1][j];
            acc00 += a0*b0; acc01 += a0*b1; acc10 += a1*b0; acc11 += a1*b1;
        }
        __syncthreads();
    }
    const float accs[2][2] = { {acc00, acc01}, {acc10, acc11} };
#pragma unroll
    for (int ii = 0; ii < 2; ii++)
#pragma unroll
        for (int jj = 0; jj < 2; jj++) {
            const int i = i0 + ty*2 + ii;
            const int h = h0 + tx*2 + jj;
            const float v = accs[ii][jj] + ee[(size_t)i * SEQ_ * HID_ + h];
            g_act[i][h] = (v >= 0.f) ? v : alpha[h] * v;
        }
}

__global__ __launch_bounds__(256) void k4_full(
    const float* __restrict__ Rw, float* __restrict__ out)
{
    if (g_flag) return;
    const int w = (blockIdx.x * 256 + threadIdx.x) >> 5;
    if (w >= B_ * NL_) return;
    const int i = w / NL_;
    const int l = w % NL_;
    const int lane = threadIdx.x & 31;
    float s = 0.f;
#pragma unroll 8
    for (int j = lane; j < HID_; j += 32)
        s += g_act[i][j] * Rw[l * HID_ + j];
#pragma unroll
    for (int off = 16; off > 0; off >>= 1)
        s += __shfl_xor_sync(0xffffffffu, s, off);
    if (lane == 0) out[i * NL_ + l] = s;
}

// ---------------------------------------------------------------------------
extern "C" void kernel_launch(void* const* d_in, const int* in_sizes, int n_in,
                              void* d_out, int out_size)
{
    const float* ee = (const float*)d_in[0];   // (256,128,1024)
    const float* S  = (const float*)d_in[1];   // (256, 256*1024)
    const float* Hw = (const float*)d_in[2];   // (1024,1024)
    const float* Rw = (const float*)d_in[3];   // (3,1024)
    const float* al = (const float*)d_in[4];   // (1024,)
    float* out = (float*)d_out;                // (256,3)

    k1_partials<<<dim3(NB_ / G_, CHUNKS_), 256>>>(ee, S);
    kmix<<<NB_ + NL_, 256>>>(al, Rw, Hw);
    k3_full<<<dim3(B_ / 32, HID_ / 32), 256>>>(ee, Hw, al);
    k4_full<<<(B_ * NL_ * 32) / 256, 256>>>(Rw, out);
    k_fast<<<(B_ * NL_ * 32) / 256, 256>>>(ee, Rw, out);
}